// round 15
// baseline (speedup 1.0000x reference)
#include <cuda_runtime.h>

// ---------------- problem constants ----------------
constexpr int NB    = 8;
constexpr int NT    = 5;
constexpr int NL    = 16;
constexpr int NTEST = NB * NL;          // 128
constexpr int NCLS  = 100;
constexpr int FEAT  = 4096;
constexpr int CHW   = 3 * 64 * 64;

constexpr int OFF_W0 = 0;        constexpr int SZ_W0 = 32 * 3 * 9;
constexpr int OFF_B0 = 864;      constexpr int SZ_B0 = 32;
constexpr int OFF_W1 = 896;      constexpr int SZ_W1 = 64 * 32 * 9;
constexpr int OFF_B1 = 19328;    constexpr int SZ_B1 = 64;
constexpr int OFF_W2 = 19392;    constexpr int SZ_W2 = 128 * 64 * 9;
constexpr int OFF_B2 = 93120;    constexpr int SZ_B2 = 128;
constexpr int OFF_W3 = 93248;    constexpr int SZ_W3 = 256 * 128 * 9;
constexpr int OFF_B3 = 388160;   constexpr int SZ_B3 = 256;
constexpr int OFF_W4 = 388416;   constexpr int SZ_W4 = 256 * 256 * 9;
constexpr int OFF_B4 = 978240;   constexpr int SZ_B4 = 256;
constexpr int OFF_WO = 978496;   constexpr int SZ_WO = NCLS * FEAT;
constexpr int OFF_BO = 1388096;  constexpr int SZ_BO = NCLS;
constexpr int PTOT   = 1388196;

// ---------------- static device scratch ----------------
__device__ float g_fw  [NB * PTOT];
__device__ float g_a1[NB * 131072];
__device__ float g_a2[NB * 65536];
__device__ float g_a3[NB * 32768];
__device__ float g_a4[NB * 16384];
__device__ float g_a5[NB * 4096];
__device__ float g_feat[NB * FEAT];
__device__ float g_logit[NB * NCLS];
__device__ float g_dlogit[NB * NCLS];
__device__ float g_d1[NB * 4096];      // dz at a5
__device__ float g_za[NB * 16384];     // dz at a4
__device__ float g_zb[NB * 32768];     // dz at a3
__device__ float g_zc[NB * 65536];     // dz at a2
__device__ float g_zd[NB * 131072];    // dz at a1
__device__ float g_d2[NB * 131072];    // raw buffer A (head, L3, L1)
__device__ float g_ta[NTEST * 131072]; // test ping; raw buffer B (L4, L2) in inner loop
__device__ float g_tb[NTEST * 131072];

// ---------------- kernels ----------------
__global__ void k_bcast_all(const float* __restrict__ w0, const float* __restrict__ b0,
                            const float* __restrict__ w1, const float* __restrict__ b1,
                            const float* __restrict__ w2, const float* __restrict__ b2,
                            const float* __restrict__ w3, const float* __restrict__ b3,
                            const float* __restrict__ w4, const float* __restrict__ b4,
                            const float* __restrict__ wo, const float* __restrict__ bo,
                            float* __restrict__ fw)
{
    long i = blockIdx.x * 256L + threadIdx.x;
    if (i >= (long)NB * PTOT) return;
    int j = (int)(i % PTOT);
    const float* src; int off;
    if      (j < OFF_B0) { src = w0; off = OFF_W0; }
    else if (j < OFF_W1) { src = b0; off = OFF_B0; }
    else if (j < OFF_B1) { src = w1; off = OFF_W1; }
    else if (j < OFF_W2) { src = b1; off = OFF_B1; }
    else if (j < OFF_B2) { src = w2; off = OFF_W2; }
    else if (j < OFF_W3) { src = b2; off = OFF_B2; }
    else if (j < OFF_B3) { src = w3; off = OFF_W3; }
    else if (j < OFF_W4) { src = b3; off = OFF_B3; }
    else if (j < OFF_B4) { src = w4; off = OFF_W4; }
    else if (j < OFF_WO) { src = b4; off = OFF_B4; }
    else if (j < OFF_BO) { src = wo; off = OFF_WO; }
    else                 { src = bo; off = OFF_BO; }
    fw[i] = src[j - off];
}

template<int S, int TOC, int TOX>
__global__ void k_conv_fwd_t(const float* __restrict__ in, long in_stride,
                             const float* __restrict__ fw, int woff, int boff, int wdiv,
                             float* __restrict__ out,
                             int N, int IC, int OC, int IH, int IW, int OH, int OW)
{
    constexpr int XLEN = (TOX - 1) * S + 3;
    int idx = blockIdx.x * 256 + threadIdx.x;
    int nox = OW / TOX;
    int noc = OC / TOC;
    if (idx >= N * noc * OH * nox) return;
    int ox0 = (idx % nox) * TOX; int t = idx / nox;
    int oy  = t % OH;            t /= OH;
    int oc0 = (t % noc) * TOC;   int n = t / noc;
    long ex = n / wdiv;
    const float* wbase = fw + ex * PTOT + woff;
    const float* x     = in + (long)n * in_stride;

    float acc[TOC][TOX];
#pragma unroll
    for (int i = 0; i < TOC; i++) {
        float bv = fw[ex * PTOT + boff + oc0 + i];
#pragma unroll
        for (int j = 0; j < TOX; j++) acc[i][j] = bv;
    }
    int ixb = ox0 * S - 1;
    for (int ic = 0; ic < IC; ic++) {
        const float* xc = x + (long)ic * IH * IW;
#pragma unroll
        for (int ky = 0; ky < 3; ky++) {
            int iy = oy * S - 1 + ky;
            if ((unsigned)iy >= (unsigned)IH) continue;
            const float* xr = xc + iy * IW;
            float xv[XLEN];
#pragma unroll
            for (int u = 0; u < XLEN; u++) {
                int ix = ixb + u;
                xv[u] = ((unsigned)ix < (unsigned)IW) ? xr[ix] : 0.f;
            }
#pragma unroll
            for (int i = 0; i < TOC; i++) {
                const float* wp = wbase + ((long)(oc0 + i) * IC + ic) * 9 + ky * 3;
                float w0 = wp[0], w1 = wp[1], w2 = wp[2];
#pragma unroll
                for (int j = 0; j < TOX; j++)
                    acc[i][j] = fmaf(w0, xv[j * S],
                                fmaf(w1, xv[j * S + 1],
                                fmaf(w2, xv[j * S + 2], acc[i][j])));
            }
        }
    }
#pragma unroll
    for (int i = 0; i < TOC; i++) {
        float* op = out + (((long)n * OC + oc0 + i) * OH + oy) * OW + ox0;
#pragma unroll
        for (int j = 0; j < TOX; j++) op[j] = fmaxf(acc[i][j], 0.f);
    }
}

template<int S, int TOC, int TOX>
__global__ void k_conv_fwd_chunk(const float* __restrict__ in, long in_stride,
                                 const float* __restrict__ fw, int woff, int wdiv,
                                 float* __restrict__ out,
                                 int N, int IC, int OC, int IH, int IW, int OH, int OW,
                                 int NCHUNK, int ICH)
{
    constexpr int XLEN = (TOX - 1) * S + 3;
    int nox = OW / TOX;
    int noc = OC / TOC;
    int base = N * noc * OH * nox;
    int idx = blockIdx.x * 256 + threadIdx.x;
    if (idx >= base * NCHUNK) return;
    int ch = idx / base; int r = idx % base;
    int ox0 = (r % nox) * TOX; int t = r / nox;
    int oy  = t % OH;          t /= OH;
    int oc0 = (t % noc) * TOC; int n = t / noc;
    long ex = n / wdiv;
    const float* wbase = fw + ex * PTOT + woff;
    const float* x     = in + (long)n * in_stride;

    float acc[TOC][TOX];
#pragma unroll
    for (int i = 0; i < TOC; i++)
#pragma unroll
        for (int j = 0; j < TOX; j++) acc[i][j] = 0.f;

    int ixb = ox0 * S - 1;
    int ic0 = ch * ICH;
    for (int ic = ic0; ic < ic0 + ICH; ic++) {
        const float* xc = x + (long)ic * IH * IW;
#pragma unroll
        for (int ky = 0; ky < 3; ky++) {
            int iy = oy * S - 1 + ky;
            if ((unsigned)iy >= (unsigned)IH) continue;
            const float* xr = xc + iy * IW;
            float xv[XLEN];
#pragma unroll
            for (int u = 0; u < XLEN; u++) {
                int ix = ixb + u;
                xv[u] = ((unsigned)ix < (unsigned)IW) ? xr[ix] : 0.f;
            }
#pragma unroll
            for (int i = 0; i < TOC; i++) {
                const float* wp = wbase + ((long)(oc0 + i) * IC + ic) * 9 + ky * 3;
                float w0 = wp[0], w1 = wp[1], w2 = wp[2];
#pragma unroll
                for (int j = 0; j < TOX; j++)
                    acc[i][j] = fmaf(w0, xv[j * S],
                                fmaf(w1, xv[j * S + 1],
                                fmaf(w2, xv[j * S + 2], acc[i][j])));
            }
        }
    }
#pragma unroll
    for (int i = 0; i < TOC; i++) {
        float* op = out + (((long)n * OC + oc0 + i) * OH + oy) * OW + ox0;
#pragma unroll
        for (int j = 0; j < TOX; j++) atomicAdd(op + j, acc[i][j]);
    }
}

template<int S, int ICH, int IH, int IW, int OH, int OW, int TOC, int TOX, int OCB>
__global__ void k_conv_smem(const float* __restrict__ in,
                            const float* __restrict__ fw, int woff, int boff, int wdiv,
                            float* __restrict__ out, int IC, int OC)
{
    constexpr int NPXG = (OH * OW) / TOX;
    constexpr int NOCG = OCB / TOC;
    constexpr int NTHR = NPXG * NOCG;
    constexpr int PADW = IW + 1;
    __shared__ float s_in[ICH * IH * PADW];

    int bi = blockIdx.x;
    int nblk = OC / OCB;
    int n   = bi / nblk;
    int ocb = (bi % nblk) * OCB;
    long ex = n / wdiv;
    const float* x  = in + (long)n * IC * IH * IW;
    const float* wb = fw + ex * PTOT + woff;

    int tid = threadIdx.x;
    int pxg = tid % NPXG;
    int ocg = tid / NPXG;
    int oc0 = ocb + ocg * TOC;

    int oyv[TOX], oxv[TOX];
#pragma unroll
    for (int j = 0; j < TOX; j++) {
        int p = pxg + NPXG * j;
        oyv[j] = p / OW;
        oxv[j] = p % OW;
    }

    float acc[TOC][TOX];
#pragma unroll
    for (int i = 0; i < TOC; i++)
#pragma unroll
        for (int j = 0; j < TOX; j++) acc[i][j] = 0.f;

    for (int c0 = 0; c0 < IC; c0 += ICH) {
        __syncthreads();
        for (int i = tid; i < ICH * IH * IW; i += NTHR) {
            int ic = i / (IH * IW); int r = i % (IH * IW);
            int iy = r / IW, ix = r % IW;
            s_in[(ic * IH + iy) * PADW + ix] = x[(long)(c0 + ic) * IH * IW + r];
        }
        __syncthreads();
        for (int ic = 0; ic < ICH; ic++) {
            const float* sc = s_in + ic * IH * PADW;
            const float* wic = wb + ((long)oc0 * IC + (c0 + ic)) * 9;
#pragma unroll
            for (int ky = 0; ky < 3; ky++) {
                float wr[TOC][3];
#pragma unroll
                for (int i = 0; i < TOC; i++) {
                    const float* wp = wic + (long)i * IC * 9 + ky * 3;
                    wr[i][0] = wp[0]; wr[i][1] = wp[1]; wr[i][2] = wp[2];
                }
#pragma unroll
                for (int j = 0; j < TOX; j++) {
                    int iy = oyv[j] * S + ky - 1;
                    if ((unsigned)iy >= (unsigned)IH) continue;
                    const float* srow = sc + iy * PADW;
                    int ixb = oxv[j] * S - 1;
                    float x0 = (ixb >= 0)       ? srow[ixb]     : 0.f;
                    float x1 =                    srow[ixb + 1];
                    float x2 = (ixb + 2 < IW)   ? srow[ixb + 2] : 0.f;
#pragma unroll
                    for (int i = 0; i < TOC; i++)
                        acc[i][j] = fmaf(wr[i][0], x0,
                                    fmaf(wr[i][1], x1,
                                    fmaf(wr[i][2], x2, acc[i][j])));
                }
            }
        }
    }
#pragma unroll
    for (int i = 0; i < TOC; i++) {
        float bv = fw[ex * PTOT + boff + oc0 + i];
#pragma unroll
        for (int j = 0; j < TOX; j++) {
            long o = (((long)n * OC + oc0 + i) * OH + oyv[j]) * OW + oxv[j];
            out[o] = fmaxf(acc[i][j] + bv, 0.f);
        }
    }
}

// Test L4 conv with FUSED GATE: writes gated feature directly.
__global__ void k_conv_l4_test(const float* __restrict__ in, const float* __restrict__ fw,
                               const float* __restrict__ gate, float* __restrict__ out)
{
    constexpr int IC = 256, OC = 256;
    constexpr int PADW = 9;
    constexpr int ICH = 4;
    __shared__ float sx[ICH * 8 * PADW];
    __shared__ float sw[256 * 37];

    int n  = blockIdx.x;
    long ex = n / NL;
    int oc = threadIdx.x;
    const float* x     = in + (long)n * IC * 64;
    const float* wbase = fw + ex * PTOT + OFF_W4 + (long)oc * IC * 9;
    float* swp = sw + oc * 37;

    float acc[4][4];
#pragma unroll
    for (int oy = 0; oy < 4; oy++)
#pragma unroll
        for (int ox = 0; ox < 4; ox++) acc[oy][ox] = 0.f;

    for (int c0 = 0; c0 < IC; c0 += ICH) {
        __syncthreads();
        {
            int i = threadIdx.x;
            int ic = i >> 6, r = i & 63;
            sx[(ic * 8 + (r >> 3)) * PADW + (r & 7)] = x[(long)(c0 + ic) * 64 + r];
        }
        {
            const float* wp = wbase + c0 * 9;
#pragma unroll
            for (int k = 0; k < 36; k++) swp[k] = wp[k];
        }
        __syncthreads();
#pragma unroll
        for (int ic = 0; ic < ICH; ic++) {
            float wv[9];
#pragma unroll
            for (int k = 0; k < 9; k++) wv[k] = swp[ic * 9 + k];
            const float* sxc = sx + ic * 8 * PADW;
#pragma unroll
            for (int ky = 0; ky < 3; ky++) {
                float w0 = wv[ky * 3], w1 = wv[ky * 3 + 1], w2 = wv[ky * 3 + 2];
#pragma unroll
                for (int oy = 0; oy < 4; oy++) {
                    int iy = oy * 2 + ky - 1;
                    if ((unsigned)iy >= 8u) continue;
                    const float* xr = sxc + iy * PADW;
                    float xv[9];
#pragma unroll
                    for (int u = 0; u < 9; u++) {
                        int ix = u - 1;
                        xv[u] = ((unsigned)ix < 8u) ? xr[ix] : 0.f;
                    }
#pragma unroll
                    for (int ox = 0; ox < 4; ox++)
                        acc[oy][ox] = fmaf(w0, xv[2 * ox],
                                      fmaf(w1, xv[2 * ox + 1],
                                      fmaf(w2, xv[2 * ox + 2], acc[oy][ox])));
                }
            }
        }
    }
    float bv = fw[ex * PTOT + OFF_B4 + oc];
    float* op = out + ((long)n * OC + oc) * 16;
    const float* gp = gate + (long)n * FEAT + oc * 16;
#pragma unroll
    for (int oy = 0; oy < 4; oy++)
#pragma unroll
        for (int ox = 0; ox < 4; ox++)
            op[oy * 4 + ox] = fmaxf(acc[oy][ox] + bv, 0.f) * gp[oy * 4 + ox];
}

__global__ void k_biasrelu(float* __restrict__ out, const float* __restrict__ fw,
                           int boff, int wdiv, int N, int OC, int OHW)
{
    int i = blockIdx.x * 256 + threadIdx.x;
    if (i >= N * OC * OHW) return;
    int oc = (i / OHW) % OC;
    long ex = (i / (OC * OHW)) / wdiv;
    out[i] = fmaxf(out[i] + fw[ex * PTOT + boff + oc], 0.f);
}

// inner L4 epilogue: a5 = relu(raw + bias); feat = a5 * gate  (fused)
__global__ void k_biasrelu_gate(float* __restrict__ a5raw, const float* __restrict__ fw,
                                const float* __restrict__ gate, int gstride,
                                float* __restrict__ feat)
{
    int i = blockIdx.x * 256 + threadIdx.x;
    if (i >= NB * FEAT) return;
    int m = i % FEAT, n = i / FEAT;
    int oc = m >> 4;   // FEAT = 256 oc * 16 px
    float v = fmaxf(a5raw[i] + fw[(long)n * PTOT + OFF_B4 + oc], 0.f);
    a5raw[i] = v;
    feat[i] = v * gate[(long)n * gstride + m];
}

// head fwd: ch==0 warp also adds bias (logits buffer must be pre-zeroed)
__global__ void k_head_fwd_chunk(const float* __restrict__ feat, const float* __restrict__ fw,
                                 int wdiv, float* __restrict__ logits, int N)
{
    int gt = blockIdx.x * 256 + threadIdx.x;
    int warp = gt >> 5, lane = gt & 31;
    if (warp >= N * NCLS * 4) return;
    int ch = warp & 3; int w2 = warp >> 2;
    int cls = w2 % NCLS, n = w2 / NCLS;
    long ex = n / wdiv;
    const float* w = fw + ex * PTOT + OFF_WO + (long)cls * FEAT + ch * 1024;
    const float* f = feat + (long)n * FEAT + ch * 1024;
    float acc = 0.f;
#pragma unroll 8
    for (int m = lane; m < 1024; m += 32) acc = fmaf(w[m], f[m], acc);
#pragma unroll
    for (int o = 16; o; o >>= 1) acc += __shfl_down_sync(0xffffffffu, acc, o);
    if (!lane) {
        if (ch == 0) acc += fw[ex * PTOT + OFF_BO + cls];
        atomicAdd(&logits[w2], acc);
    }
}

__global__ void k_ce_grad(const float* __restrict__ logits, const int* __restrict__ y,
                          int ystride, int yoff, float* __restrict__ dlogit,
                          float* __restrict__ fw, const float* __restrict__ log_lr)
{
    int b = blockIdx.x, tid = threadIdx.x;
    __shared__ float red[128];
    float v = (tid < NCLS) ? logits[b * NCLS + tid] : -1e30f;
    red[tid] = v; __syncthreads();
    for (int s = 64; s > 0; s >>= 1) { if (tid < s) red[tid] = fmaxf(red[tid], red[tid + s]); __syncthreads(); }
    float m = red[0]; __syncthreads();
    float e = (tid < NCLS) ? expf(v - m) : 0.f;
    red[tid] = e; __syncthreads();
    for (int s = 64; s > 0; s >>= 1) { if (tid < s) red[tid] += red[tid + s]; __syncthreads(); }
    float sum = red[0];
    int label = y[b * ystride + yoff];
    if (tid < NCLS) {
        float dl = e / sum - (tid == label ? 1.f : 0.f);
        dlogit[b * NCLS + tid] = dl;
        fw[(long)b * PTOT + OFF_BO + tid] -= expf(*log_lr) * dl;
    }
}

__global__ void k_head_bwd_f_chunk(const float* __restrict__ dlogit, const float* __restrict__ fw,
                                   float* __restrict__ raw)
{
    int i = blockIdx.x * 256 + threadIdx.x;
    if (i >= NB * 4 * FEAT) return;
    int m = i % FEAT; int t = i / FEAT;
    int ch = t % 4; int b = t / 4;
    const float* w  = fw + (long)b * PTOT + OFF_WO + m + (long)(ch * 25) * FEAT;
    const float* dl = dlogit + b * NCLS + ch * 25;
    float acc = 0.f;
#pragma unroll
    for (int n = 0; n < 25; n++) acc = fmaf(w[(long)n * FEAT], dl[n], acc);
    atomicAdd(&raw[(long)b * FEAT + m], acc);
}

__global__ void k_mask_gate(const float* __restrict__ raw, const float* __restrict__ a5,
                            const float* __restrict__ gate, int gstride, float* __restrict__ dz)
{
    int i = blockIdx.x * 256 + threadIdx.x;
    if (i >= NB * FEAT) return;
    int m = i % FEAT, b = i / FEAT;
    dz[i] = (a5[i] > 0.f) ? raw[i] * gate[(long)b * gstride + m] : 0.f;
}

__global__ void k_head_upd_w(const float* __restrict__ dlogit, const float* __restrict__ feat,
                             float* __restrict__ fw, const float* __restrict__ log_lr)
{
    int i = blockIdx.x * 256 + threadIdx.x;
    if (i >= NB * NCLS * FEAT) return;
    int m = i % FEAT; int t = i / FEAT;
    int cls = t % NCLS; int b = t / NCLS;
    fw[(long)b * PTOT + OFF_WO + (long)cls * FEAT + m] -=
        expf(*log_lr) * dlogit[b * NCLS + cls] * feat[(long)b * FEAT + m];
}

__global__ void k_bwd_b_upd(const float* __restrict__ dz, float* __restrict__ fw,
                            const float* __restrict__ log_lr, int boff, int OC, int OHW)
{
    int gt = blockIdx.x * 256 + threadIdx.x;
    int warp = gt >> 5, lane = gt & 31;
    if (warp >= NB * OC) return;
    int oc = warp % OC, b = warp / OC;
    const float* p = dz + ((long)b * OC + oc) * OHW;
    float acc = 0.f;
    for (int i = lane; i < OHW; i += 32) acc += p[i];
#pragma unroll
    for (int o = 16; o; o >>= 1) acc += __shfl_down_sync(0xffffffffu, acc, o);
    if (!lane) fw[(long)b * PTOT + boff + oc] -= expf(*log_lr) * acc;
}

template<int S>
__global__ void k_bwd_w_warp(const float* __restrict__ dz, const float* __restrict__ xin, long xstride,
                             float* __restrict__ fw, const float* __restrict__ log_lr, int woff,
                             int IC, int OC, int IH, int IW, int OH, int OW, int NCH)
{
    long gt = blockIdx.x * 256L + threadIdx.x;
    long w = gt >> 5; int lane = (int)(gt & 31);
    if (w >= (long)NB * OC * IC * NCH) return;
    int c  = (int)(w % NCH); long t = w / NCH;
    int ic = (int)(t % IC); t /= IC;
    int oc = (int)(t % OC); int b = (int)(t / OC);
    int CH = OH / NCH;
    const float* x = xin + (long)b * xstride + (long)ic * IH * IW;
    const float* z = dz + ((long)b * OC + oc) * OH * OW;
    float acc[9];
#pragma unroll
    for (int k = 0; k < 9; k++) acc[k] = 0.f;
    int oybase = c * CH;
    int npix = CH * OW;
    for (int p = lane; p < npix; p += 32) {
        int oy = oybase + p / OW;
        int ox = p % OW;
        float zv = z[oy * OW + ox];
#pragma unroll
        for (int ky = 0; ky < 3; ky++) {
            int iy = oy * S + ky - 1;
            if ((unsigned)iy >= (unsigned)IH) continue;
            const float* xr = x + iy * IW;
            int ixb = ox * S - 1;
#pragma unroll
            for (int kx = 0; kx < 3; kx++) {
                int ix = ixb + kx;
                if ((unsigned)ix < (unsigned)IW)
                    acc[ky * 3 + kx] = fmaf(zv, xr[ix], acc[ky * 3 + kx]);
            }
        }
    }
    float nlr = -expf(*log_lr);
    float* g = fw + (long)b * PTOT + woff + ((long)oc * IC + ic) * 9;
#pragma unroll
    for (int k = 0; k < 9; k++) {
        float v = acc[k];
#pragma unroll
        for (int o = 16; o; o >>= 1) v += __shfl_down_sync(0xffffffffu, v, o);
        if (!lane) atomicAdd(g + k, nlr * v);
    }
}

__global__ void k_bwd_x_chunk(const float* __restrict__ dz, const float* __restrict__ fw, int woff,
                              float* __restrict__ raw,
                              int IC, int OC, int IH, int IW, int OH, int OW,
                              int NCHUNK, int OCH)
{
    int nix = IW >> 2;
    int base = NB * IC * IH * nix;
    int idx = blockIdx.x * 256 + threadIdx.x;
    if (idx >= base * NCHUNK) return;
    int ch = idx / base; int r = idx % base;
    int ix0 = (r % nix) * 4; int t = r / nix;
    int iy = t % IH; t /= IH;
    int ic = t % IC; int b = t / IC;
    long pix = (((long)b * IC + ic) * IH + iy) * IW + ix0;

    float acc0 = 0.f, acc1 = 0.f, acc2 = 0.f, acc3 = 0.f;
    int ox0p = ix0 >> 1;
    bool ok2 = (ox0p + 2 < OW), ok1 = (ox0p + 1 < OW);

    int oyv[3]; bool kyok[3];
#pragma unroll
    for (int ky = 0; ky < 3; ky++) {
        int ty = iy + 1 - ky;
        kyok[ky] = (ty >= 0) && !(ty & 1) && ((ty >> 1) < OH);
        oyv[ky] = ty >> 1;
    }
    const float* wb = fw + (long)b * PTOT + woff + (long)ic * 9;
    const float* zb = dz + (long)b * OC * OH * OW;
    int oc0 = ch * OCH;
    for (int oc = oc0; oc < oc0 + OCH; oc++) {
        const float* wp = wb + (long)oc * IC * 9;
        const float* zp = zb + (long)oc * OH * OW;
#pragma unroll
        for (int ky = 0; ky < 3; ky++) {
            if (!kyok[ky]) continue;
            const float* zr = zp + oyv[ky] * OW;
            float d0 = zr[ox0p];
            float d1 = ok1 ? zr[ox0p + 1] : 0.f;
            float d2 = ok2 ? zr[ox0p + 2] : 0.f;
            float wk0 = wp[ky * 3 + 0], wk1 = wp[ky * 3 + 1], wk2 = wp[ky * 3 + 2];
            acc0 = fmaf(wk1, d0, acc0);
            acc1 = fmaf(wk0, d1, fmaf(wk2, d0, acc1));
            acc2 = fmaf(wk1, d1, acc2);
            acc3 = fmaf(wk0, d2, fmaf(wk2, d1, acc3));
        }
    }
    atomicAdd(&raw[pix],     acc0);
    atomicAdd(&raw[pix + 1], acc1);
    atomicAdd(&raw[pix + 2], acc2);
    atomicAdd(&raw[pix + 3], acc3);
}

__global__ void k_mask(const float* __restrict__ raw, const float* __restrict__ act,
                       float* __restrict__ dz, int count)
{
    int i = blockIdx.x * 256 + threadIdx.x;
    if (i < count) dz[i] = (act[i] > 0.f) ? raw[i] : 0.f;
}

__global__ void k_loss_eval(const float* __restrict__ logits, const int* __restrict__ y,
                            const float* __restrict__ log_lr, float* __restrict__ out)
{
    int e = blockIdx.x, tid = threadIdx.x;
    __shared__ float rv[128];
    __shared__ int   ri[128];
    float v = (tid < NCLS) ? logits[e * NCLS + tid] : -1e30f;
    rv[tid] = v; ri[tid] = tid; __syncthreads();
    for (int s = 64; s > 0; s >>= 1) {
        if (tid < s) {
            if (rv[tid + s] > rv[tid] || (rv[tid + s] == rv[tid] && ri[tid + s] < ri[tid])) {
                rv[tid] = rv[tid + s]; ri[tid] = ri[tid + s];
            }
        }
        __syncthreads();
    }
    float m = rv[0]; int amax = ri[0]; __syncthreads();
    float ex = (tid < NCLS) ? expf(v - m) : 0.f;
    rv[tid] = ex; __syncthreads();
    for (int s = 64; s > 0; s >>= 1) { if (tid < s) rv[tid] += rv[tid + s]; __syncthreads(); }
    if (tid == 0) {
        float lse = m + logf(rv[0]);
        int label = y[e];
        out[e]        = lse - logits[e * NCLS + label];
        out[129 + e]  = (amax == label) ? 1.f : 0.f;
        if (e == 0) out[128] = expf(*log_lr);
    }
}

// ---------------- launcher ----------------
struct LC { int ic, oc, ih, iw, oh, ow, s; };
static const LC lc[5] = {
    {  3,  32, 64, 64, 64, 64, 1},
    { 32,  64, 64, 64, 32, 32, 2},
    { 64, 128, 32, 32, 16, 16, 2},
    {128, 256, 16, 16,  8,  8, 2},
    {256, 256,  8,  8,  4,  4, 2},
};
static const int woffs[5] = {OFF_W0, OFF_W1, OFF_W2, OFF_W3, OFF_W4};
static const int boffs[5] = {OFF_B0, OFF_B1, OFF_B2, OFF_B3, OFF_B4};

static inline unsigned GRID(long n) { return (unsigned)((n + 255) / 256); }

extern "C" void kernel_launch(void* const* d_in, const int* in_sizes, int n_in,
                              void* d_out, int out_size)
{
    const float* pw[12];
    for (int i = 0; i < 12; i++) pw[i] = (const float*)d_in[i];
    const float* log_lr     = (const float*)d_in[12];
    const float* train_x    = (const float*)d_in[13];
    const float* test_x     = (const float*)d_in[14];
    const float* train_gate = (const float*)d_in[15];
    const float* test_gate  = (const float*)d_in[16];
    const int*   train_y    = (const int*)d_in[17];
    const int*   test_y     = (const int*)d_in[18];
    float* out = (float*)d_out;

    float *fw, *a1, *a2, *a3, *a4, *a5, *feat, *logit, *dlogit, *d1, *d2, *za, *zb, *zc, *zd, *ta, *tb;
    cudaGetSymbolAddress((void**)&fw,     g_fw);
    cudaGetSymbolAddress((void**)&a1,     g_a1);
    cudaGetSymbolAddress((void**)&a2,     g_a2);
    cudaGetSymbolAddress((void**)&a3,     g_a3);
    cudaGetSymbolAddress((void**)&a4,     g_a4);
    cudaGetSymbolAddress((void**)&a5,     g_a5);
    cudaGetSymbolAddress((void**)&feat,   g_feat);
    cudaGetSymbolAddress((void**)&logit,  g_logit);
    cudaGetSymbolAddress((void**)&dlogit, g_dlogit);
    cudaGetSymbolAddress((void**)&d1,     g_d1);
    cudaGetSymbolAddress((void**)&d2,     g_d2);
    cudaGetSymbolAddress((void**)&za,     g_za);
    cudaGetSymbolAddress((void**)&zb,     g_zb);
    cudaGetSymbolAddress((void**)&zc,     g_zc);
    cudaGetSymbolAddress((void**)&zd,     g_zd);
    cudaGetSymbolAddress((void**)&ta,     g_ta);
    cudaGetSymbolAddress((void**)&tb,     g_tb);

    static cudaStream_t s_side = nullptr;
    static cudaEvent_t  ev_fork = nullptr, ev_fz = nullptr, ev_h = nullptr,
                        ev_x1 = nullptr, ev_x2 = nullptr, ev_x3 = nullptr, ev_x4 = nullptr,
                        ev_mg = nullptr, ev_m4 = nullptr, ev_m3 = nullptr, ev_m1 = nullptr,
                        ev_z3 = nullptr, ev_z2 = nullptr, ev_z1 = nullptr, ev_done = nullptr;
    if (!s_side) {
        cudaStreamCreateWithFlags(&s_side, cudaStreamNonBlocking);
        cudaEventCreateWithFlags(&ev_fork, cudaEventDisableTiming);
        cudaEventCreateWithFlags(&ev_fz,   cudaEventDisableTiming);
        cudaEventCreateWithFlags(&ev_h,    cudaEventDisableTiming);
        cudaEventCreateWithFlags(&ev_x1,   cudaEventDisableTiming);
        cudaEventCreateWithFlags(&ev_x2,   cudaEventDisableTiming);
        cudaEventCreateWithFlags(&ev_x3,   cudaEventDisableTiming);
        cudaEventCreateWithFlags(&ev_x4,   cudaEventDisableTiming);
        cudaEventCreateWithFlags(&ev_mg,   cudaEventDisableTiming);
        cudaEventCreateWithFlags(&ev_m4,   cudaEventDisableTiming);
        cudaEventCreateWithFlags(&ev_m3,   cudaEventDisableTiming);
        cudaEventCreateWithFlags(&ev_m1,   cudaEventDisableTiming);
        cudaEventCreateWithFlags(&ev_z3,   cudaEventDisableTiming);
        cudaEventCreateWithFlags(&ev_z2,   cudaEventDisableTiming);
        cudaEventCreateWithFlags(&ev_z1,   cudaEventDisableTiming);
        cudaEventCreateWithFlags(&ev_done, cudaEventDisableTiming);
    }
    cudaEvent_t ev_x[5] = {nullptr, ev_x1, ev_x2, ev_x3, ev_x4};

    float* acts[6] = {nullptr, a1, a2, a3, a4, a5};
    float* zbuf[5] = {zd, zc, zb, za, d1};
    float* rawb[5] = {nullptr, d2, ta, d2, ta};
    long insz[5];
    for (int j = 0; j < 5; j++) insz[j] = (long)NB * lc[j].ic * lc[j].ih * lc[j].iw;

    const int f_ich[5] = {0, 8, 8, 8, 4};
    const int wnch[5] = {16, 4, 2, 1, 1};

    k_bcast_all<<<GRID((long)NB * PTOT), 256>>>(pw[0], pw[1], pw[2], pw[3], pw[4], pw[5],
                                                pw[6], pw[7], pw[8], pw[9], pw[10], pw[11], fw);

    auto fwd_inner_conv = [&](int j, const float* in, float* o) {
        const LC& L = lc[j];
        int ich = f_ich[j], nch = L.ic / ich;
        long instr = (long)L.ic * L.ih * L.iw;
        long tot = (long)NB * (L.oc / 4) * L.oh * (L.ow / 4) * nch;
        k_conv_fwd_chunk<2, 4, 4><<<GRID(tot), 256>>>(in, instr, fw, woffs[j], 1, o,
            NB, L.ic, L.oc, L.ih, L.iw, L.oh, L.ow, nch, ich);
    };

    for (int t = 0; t < NT; t++) {
        const float* in0 = train_x + (long)t * CHW;

        // fork: memsets (+ logit zero) on side while L0 conv runs on main
        cudaEventRecord(ev_fork, 0);
        cudaStreamWaitEvent(s_side, ev_fork, 0);
        cudaMemsetAsync(a2, 0, (long)NB * 65536 * sizeof(float), s_side);
        cudaMemsetAsync(a3, 0, (long)NB * 32768 * sizeof(float), s_side);
        cudaMemsetAsync(a4, 0, (long)NB * 16384 * sizeof(float), s_side);
        cudaMemsetAsync(a5, 0, (long)NB * 4096 * sizeof(float), s_side);
        cudaMemsetAsync(d2, 0, (long)NB * FEAT * sizeof(float), s_side);   // head raw
        cudaMemsetAsync(ta, 0, insz[4] * sizeof(float), s_side);           // L4 raw
        cudaMemsetAsync(logit, 0, (long)NB * NCLS * sizeof(float), s_side);
        cudaEventRecord(ev_fz, s_side);
        {
            long tot = (long)NB * (32 / 4) * 64 * (64 / 4);
            k_conv_fwd_t<1, 4, 4><<<GRID(tot), 256>>>(in0, (long)NT * CHW, fw, OFF_W0, OFF_B0, 1, a1,
                                                      NB, 3, 32, 64, 64, 64, 64);
        }
        cudaStreamWaitEvent(0, ev_fz, 0);
        fwd_inner_conv(1, a1, a2);
        k_biasrelu<<<GRID((long)NB * 65536), 256>>>(a2, fw, boffs[1], 1, NB, 64, 32 * 32);
        fwd_inner_conv(2, a2, a3);
        k_biasrelu<<<GRID((long)NB * 32768), 256>>>(a3, fw, boffs[2], 1, NB, 128, 16 * 16);
        fwd_inner_conv(3, a3, a4);
        k_biasrelu<<<GRID((long)NB * 16384), 256>>>(a4, fw, boffs[3], 1, NB, 256, 8 * 8);
        fwd_inner_conv(4, a4, a5);
        // fused: bias+relu (a5) + gate (feat)
        k_biasrelu_gate<<<GRID((long)NB * FEAT), 256>>>(a5, fw, train_gate + (long)t * FEAT,
                                                        NT * FEAT, feat);
        k_head_fwd_chunk<<<GRID((long)NB * NCLS * 4 * 32), 256>>>(feat, fw, 1, logit, NB);
        k_ce_grad<<<NB, 128>>>(logit, train_y, NT, t, dlogit, fw, log_lr);
        k_head_bwd_f_chunk<<<GRID((long)NB * 4 * FEAT), 256>>>(dlogit, fw, d2);
        cudaEventRecord(ev_h, 0);
        cudaStreamWaitEvent(s_side, ev_h, 0);
        k_head_upd_w<<<GRID((long)NB * NCLS * FEAT), 256, 0, s_side>>>(dlogit, feat, fw, log_lr);
        k_mask_gate<<<GRID((long)NB * FEAT), 256>>>(d2, a5, train_gate + (long)t * FEAT, NT * FEAT, d1);
        cudaEventRecord(ev_mg, 0);
        cudaStreamWaitEvent(s_side, ev_mg, 0);
        cudaMemsetAsync(d2, 0, insz[3] * sizeof(float), s_side);
        cudaEventRecord(ev_z3, s_side);

        for (int j = 4; j >= 1; j--) {
            const LC& L = lc[j];
            long instr = (long)L.ic * L.ih * L.iw;
            if (j == 3) cudaStreamWaitEvent(0, ev_z3, 0);
            if (j == 2) cudaStreamWaitEvent(0, ev_z2, 0);
            if (j == 1) cudaStreamWaitEvent(0, ev_z1, 0);
            {
                int och = 16, nch = L.oc / och;
                long tot = (long)NB * L.ic * L.ih * (L.iw / 4) * nch;
                k_bwd_x_chunk<<<GRID(tot), 256>>>(zbuf[j], fw, woffs[j], rawb[j],
                    L.ic, L.oc, L.ih, L.iw, L.oh, L.ow, nch, och);
            }
            cudaEventRecord(ev_x[j], 0);
            cudaStreamWaitEvent(s_side, ev_x[j], 0);
            k_bwd_b_upd<<<GRID((long)NB * L.oc * 32), 256, 0, s_side>>>(zbuf[j], fw, log_lr,
                                                                        boffs[j], L.oc, L.oh * L.ow);
            {
                long warps = (long)NB * L.oc * L.ic * wnch[j];
                k_bwd_w_warp<2><<<GRID(warps * 32), 256, 0, s_side>>>(zbuf[j], acts[j], instr,
                    fw, log_lr, woffs[j], L.ic, L.oc, L.ih, L.iw, L.oh, L.ow, wnch[j]);
            }
            k_mask<<<GRID(insz[j]), 256>>>(rawb[j], acts[j], zbuf[j - 1], (int)insz[j]);
            if (j == 4) {
                cudaEventRecord(ev_m4, 0);
                cudaStreamWaitEvent(s_side, ev_m4, 0);
                cudaMemsetAsync(ta, 0, insz[2] * sizeof(float), s_side);
                cudaEventRecord(ev_z2, s_side);
            } else if (j == 3) {
                cudaEventRecord(ev_m3, 0);
                cudaStreamWaitEvent(s_side, ev_m3, 0);
                cudaMemsetAsync(d2, 0, insz[1] * sizeof(float), s_side);
                cudaEventRecord(ev_z1, s_side);
            }
        }
        cudaEventRecord(ev_m1, 0);
        cudaStreamWaitEvent(s_side, ev_m1, 0);
        k_bwd_b_upd<<<GRID((long)NB * 32 * 32), 256, 0, s_side>>>(zbuf[0], fw, log_lr, OFF_B0, 32, 4096);
        {
            long warps = (long)NB * 32 * 3 * wnch[0];
            k_bwd_w_warp<1><<<GRID(warps * 32), 256, 0, s_side>>>(zbuf[0], in0, (long)NT * CHW,
                fw, log_lr, OFF_W0, 3, 32, 64, 64, 64, 64, wnch[0]);
        }
        cudaEventRecord(ev_done, s_side);
        cudaStreamWaitEvent(0, ev_done, 0);
    }

    // -------- test forward --------
    cudaMemsetAsync(out + 257, 0, (long)NTEST * NCLS * sizeof(float));   // test logits = 0
    {
        long tot = (long)NTEST * (32 / 4) * 64 * (64 / 4);
        k_conv_fwd_t<1, 4, 4><<<GRID(tot), 256>>>(test_x, (long)CHW, fw, OFF_W0, OFF_B0, NL, ta,
                                                  NTEST, 3, 32, 64, 64, 64, 64);
    }
    k_conv_smem<2, 4, 64, 64, 32, 32, 8, 4, 8><<<NTEST * (64 / 8), 256>>>(
        ta, fw, OFF_W1, OFF_B1, NL, tb, 32, 64);
    k_conv_smem<2, 8, 32, 32, 16, 16, 8, 4, 32><<<NTEST * (128 / 32), 256>>>(
        tb, fw, OFF_W2, OFF_B2, NL, ta, 64, 128);
    k_conv_smem<2, 32, 16, 16, 8, 8, 8, 4, 128><<<NTEST * (256 / 128), 256>>>(
        ta, fw, OFF_W3, OFF_B3, NL, tb, 128, 256);
    // L4 with fused gate: reads tb (L3 out), writes gated feature into ta
    k_conv_l4_test<<<NTEST, 256>>>(tb, fw, test_gate, ta);
    k_head_fwd_chunk<<<GRID((long)NTEST * NCLS * 4 * 32), 256>>>(ta, fw, NL, out + 257, NTEST);
    k_loss_eval<<<NTEST, 128>>>(out + 257, test_y, log_lr, out);
}

// round 16
// speedup vs baseline: 1.0423x; 1.0423x over previous
#include <cuda_runtime.h>

// ---------------- problem constants ----------------
constexpr int NB    = 8;
constexpr int NT    = 5;
constexpr int NL    = 16;
constexpr int NTEST = NB * NL;          // 128
constexpr int NCLS  = 100;
constexpr int FEAT  = 4096;
constexpr int CHW   = 3 * 64 * 64;

constexpr int OFF_W0 = 0;        constexpr int SZ_W0 = 32 * 3 * 9;
constexpr int OFF_B0 = 864;      constexpr int SZ_B0 = 32;
constexpr int OFF_W1 = 896;      constexpr int SZ_W1 = 64 * 32 * 9;
constexpr int OFF_B1 = 19328;    constexpr int SZ_B1 = 64;
constexpr int OFF_W2 = 19392;    constexpr int SZ_W2 = 128 * 64 * 9;
constexpr int OFF_B2 = 93120;    constexpr int SZ_B2 = 128;
constexpr int OFF_W3 = 93248;    constexpr int SZ_W3 = 256 * 128 * 9;
constexpr int OFF_B3 = 388160;   constexpr int SZ_B3 = 256;
constexpr int OFF_W4 = 388416;   constexpr int SZ_W4 = 256 * 256 * 9;
constexpr int OFF_B4 = 978240;   constexpr int SZ_B4 = 256;
constexpr int OFF_WO = 978496;   constexpr int SZ_WO = NCLS * FEAT;
constexpr int OFF_BO = 1388096;  constexpr int SZ_BO = NCLS;
constexpr int PTOT   = 1388196;

// ---------------- static device scratch ----------------
__device__ float g_fw  [NB * PTOT];
__device__ float g_a1[NB * 131072];
__device__ float g_a2[NB * 65536];
__device__ float g_a3[NB * 32768];
__device__ float g_a4[NB * 16384];
__device__ float g_a5[NB * 4096];
__device__ float g_feat[NB * FEAT];
__device__ float g_logit[NB * NCLS];
__device__ float g_dlogit[NB * NCLS];
__device__ float g_d1[NB * 4096];      // dz at a5
__device__ float g_za[NB * 16384];     // dz at a4
__device__ float g_zb[NB * 32768];     // dz at a3
__device__ float g_zc[NB * 65536];     // dz at a2
__device__ float g_zd[NB * 131072];    // dz at a1
__device__ float g_d2[NB * 131072];    // raw buffer A (head, L3, L1)
__device__ float g_ta[NTEST * 131072]; // test ping; raw buffer B (L4, L2) in inner loop
__device__ float g_tb[NTEST * 131072];

// ---------------- kernels ----------------
__global__ void k_bcast_all(const float* __restrict__ w0, const float* __restrict__ b0,
                            const float* __restrict__ w1, const float* __restrict__ b1,
                            const float* __restrict__ w2, const float* __restrict__ b2,
                            const float* __restrict__ w3, const float* __restrict__ b3,
                            const float* __restrict__ w4, const float* __restrict__ b4,
                            const float* __restrict__ wo, const float* __restrict__ bo,
                            float* __restrict__ fw)
{
    long i = blockIdx.x * 256L + threadIdx.x;
    if (i >= (long)NB * PTOT) return;
    int j = (int)(i % PTOT);
    const float* src; int off;
    if      (j < OFF_B0) { src = w0; off = OFF_W0; }
    else if (j < OFF_W1) { src = b0; off = OFF_B0; }
    else if (j < OFF_B1) { src = w1; off = OFF_W1; }
    else if (j < OFF_W2) { src = b1; off = OFF_B1; }
    else if (j < OFF_B2) { src = w2; off = OFF_W2; }
    else if (j < OFF_W3) { src = b2; off = OFF_B2; }
    else if (j < OFF_B3) { src = w3; off = OFF_W3; }
    else if (j < OFF_W4) { src = b3; off = OFF_B3; }
    else if (j < OFF_B4) { src = w4; off = OFF_W4; }
    else if (j < OFF_WO) { src = b4; off = OFF_B4; }
    else if (j < OFF_BO) { src = wo; off = OFF_WO; }
    else                 { src = bo; off = OFF_BO; }
    fw[i] = src[j - off];
}

// Direct tiled conv fwd, fused bias+relu. S==1/TOX==4 path uses a float4 core load.
template<int S, int TOC, int TOX>
__global__ void k_conv_fwd_t(const float* __restrict__ in, long in_stride,
                             const float* __restrict__ fw, int woff, int boff, int wdiv,
                             float* __restrict__ out,
                             int N, int IC, int OC, int IH, int IW, int OH, int OW)
{
    constexpr int XLEN = (TOX - 1) * S + 3;
    int idx = blockIdx.x * 256 + threadIdx.x;
    int nox = OW / TOX;
    int noc = OC / TOC;
    if (idx >= N * noc * OH * nox) return;
    int ox0 = (idx % nox) * TOX; int t = idx / nox;
    int oy  = t % OH;            t /= OH;
    int oc0 = (t % noc) * TOC;   int n = t / noc;
    long ex = n / wdiv;
    const float* wbase = fw + ex * PTOT + woff;
    const float* x     = in + (long)n * in_stride;

    float acc[TOC][TOX];
#pragma unroll
    for (int i = 0; i < TOC; i++) {
        float bv = fw[ex * PTOT + boff + oc0 + i];
#pragma unroll
        for (int j = 0; j < TOX; j++) acc[i][j] = bv;
    }
    int ixb = ox0 * S - 1;
    for (int ic = 0; ic < IC; ic++) {
        const float* xc = x + (long)ic * IH * IW;
#pragma unroll
        for (int ky = 0; ky < 3; ky++) {
            int iy = oy * S - 1 + ky;
            if ((unsigned)iy >= (unsigned)IH) continue;
            const float* xr = xc + iy * IW;
            float xv[XLEN];
            if (S == 1 && TOX == 4) {
                // xv[1..4] = aligned float4 at xr+ox0 (ox0 % 4 == 0)
                float4 v = *reinterpret_cast<const float4*>(xr + ixb + 1);
                xv[0] = (ixb >= 0) ? xr[ixb] : 0.f;
                xv[1] = v.x; xv[2] = v.y; xv[3] = v.z; xv[4] = v.w;
                int ix5 = ixb + 5;
                xv[5] = (ix5 < IW) ? xr[ix5] : 0.f;
            } else {
#pragma unroll
                for (int u = 0; u < XLEN; u++) {
                    int ix = ixb + u;
                    xv[u] = ((unsigned)ix < (unsigned)IW) ? xr[ix] : 0.f;
                }
            }
#pragma unroll
            for (int i = 0; i < TOC; i++) {
                const float* wp = wbase + ((long)(oc0 + i) * IC + ic) * 9 + ky * 3;
                float w0 = wp[0], w1 = wp[1], w2 = wp[2];
#pragma unroll
                for (int j = 0; j < TOX; j++)
                    acc[i][j] = fmaf(w0, xv[j * S],
                                fmaf(w1, xv[j * S + 1],
                                fmaf(w2, xv[j * S + 2], acc[i][j])));
            }
        }
    }
#pragma unroll
    for (int i = 0; i < TOC; i++) {
        float* op = out + (((long)n * OC + oc0 + i) * OH + oy) * OW + ox0;
#pragma unroll
        for (int j = 0; j < TOX; j++) op[j] = fmaxf(acc[i][j], 0.f);
    }
}

// IC-chunked conv fwd (inner loop): S==2/TOX==4 path uses two aligned float4 loads.
template<int S, int TOC, int TOX>
__global__ void k_conv_fwd_chunk(const float* __restrict__ in, long in_stride,
                                 const float* __restrict__ fw, int woff, int wdiv,
                                 float* __restrict__ out,
                                 int N, int IC, int OC, int IH, int IW, int OH, int OW,
                                 int NCHUNK, int ICH)
{
    constexpr int XLEN = (TOX - 1) * S + 3;
    int nox = OW / TOX;
    int noc = OC / TOC;
    int base = N * noc * OH * nox;
    int idx = blockIdx.x * 256 + threadIdx.x;
    if (idx >= base * NCHUNK) return;
    int ch = idx / base; int r = idx % base;
    int ox0 = (r % nox) * TOX; int t = r / nox;
    int oy  = t % OH;          t /= OH;
    int oc0 = (t % noc) * TOC; int n = t / noc;
    long ex = n / wdiv;
    const float* wbase = fw + ex * PTOT + woff;
    const float* x     = in + (long)n * in_stride;

    float acc[TOC][TOX];
#pragma unroll
    for (int i = 0; i < TOC; i++)
#pragma unroll
        for (int j = 0; j < TOX; j++) acc[i][j] = 0.f;

    int ixb = ox0 * S - 1;
    int ic0 = ch * ICH;
    for (int ic = ic0; ic < ic0 + ICH; ic++) {
        const float* xc = x + (long)ic * IH * IW;
#pragma unroll
        for (int ky = 0; ky < 3; ky++) {
            int iy = oy * S - 1 + ky;
            if ((unsigned)iy >= (unsigned)IH) continue;
            const float* xr = xc + iy * IW;
            float xv[XLEN];
            if (S == 2 && TOX == 4) {
                // ixb+1 = ox0*2, multiple of 8 -> 32B aligned; ixb+8 <= IW-1 always
                float4 v0 = *reinterpret_cast<const float4*>(xr + ixb + 1);
                float4 v1 = *reinterpret_cast<const float4*>(xr + ixb + 5);
                xv[0] = (ixb >= 0) ? xr[ixb] : 0.f;
                xv[1] = v0.x; xv[2] = v0.y; xv[3] = v0.z; xv[4] = v0.w;
                xv[5] = v1.x; xv[6] = v1.y; xv[7] = v1.z; xv[8] = v1.w;
            } else {
#pragma unroll
                for (int u = 0; u < XLEN; u++) {
                    int ix = ixb + u;
                    xv[u] = ((unsigned)ix < (unsigned)IW) ? xr[ix] : 0.f;
                }
            }
#pragma unroll
            for (int i = 0; i < TOC; i++) {
                const float* wp = wbase + ((long)(oc0 + i) * IC + ic) * 9 + ky * 3;
                float w0 = wp[0], w1 = wp[1], w2 = wp[2];
#pragma unroll
                for (int j = 0; j < TOX; j++)
                    acc[i][j] = fmaf(w0, xv[j * S],
                                fmaf(w1, xv[j * S + 1],
                                fmaf(w2, xv[j * S + 2], acc[i][j])));
            }
        }
    }
#pragma unroll
    for (int i = 0; i < TOC; i++) {
        float* op = out + (((long)n * OC + oc0 + i) * OH + oy) * OW + ox0;
#pragma unroll
        for (int j = 0; j < TOX; j++) atomicAdd(op + j, acc[i][j]);
    }
}

template<int S, int ICH, int IH, int IW, int OH, int OW, int TOC, int TOX, int OCB>
__global__ void k_conv_smem(const float* __restrict__ in,
                            const float* __restrict__ fw, int woff, int boff, int wdiv,
                            float* __restrict__ out, int IC, int OC)
{
    constexpr int NPXG = (OH * OW) / TOX;
    constexpr int NOCG = OCB / TOC;
    constexpr int NTHR = NPXG * NOCG;
    constexpr int PADW = IW + 1;
    __shared__ float s_in[ICH * IH * PADW];

    int bi = blockIdx.x;
    int nblk = OC / OCB;
    int n   = bi / nblk;
    int ocb = (bi % nblk) * OCB;
    long ex = n / wdiv;
    const float* x  = in + (long)n * IC * IH * IW;
    const float* wb = fw + ex * PTOT + woff;

    int tid = threadIdx.x;
    int pxg = tid % NPXG;
    int ocg = tid / NPXG;
    int oc0 = ocb + ocg * TOC;

    int oyv[TOX], oxv[TOX];
#pragma unroll
    for (int j = 0; j < TOX; j++) {
        int p = pxg + NPXG * j;
        oyv[j] = p / OW;
        oxv[j] = p % OW;
    }

    float acc[TOC][TOX];
#pragma unroll
    for (int i = 0; i < TOC; i++)
#pragma unroll
        for (int j = 0; j < TOX; j++) acc[i][j] = 0.f;

    for (int c0 = 0; c0 < IC; c0 += ICH) {
        __syncthreads();
        for (int i = tid; i < ICH * IH * IW; i += NTHR) {
            int ic = i / (IH * IW); int r = i % (IH * IW);
            int iy = r / IW, ix = r % IW;
            s_in[(ic * IH + iy) * PADW + ix] = x[(long)(c0 + ic) * IH * IW + r];
        }
        __syncthreads();
        for (int ic = 0; ic < ICH; ic++) {
            const float* sc = s_in + ic * IH * PADW;
            const float* wic = wb + ((long)oc0 * IC + (c0 + ic)) * 9;
#pragma unroll
            for (int ky = 0; ky < 3; ky++) {
                float wr[TOC][3];
#pragma unroll
                for (int i = 0; i < TOC; i++) {
                    const float* wp = wic + (long)i * IC * 9 + ky * 3;
                    wr[i][0] = wp[0]; wr[i][1] = wp[1]; wr[i][2] = wp[2];
                }
#pragma unroll
                for (int j = 0; j < TOX; j++) {
                    int iy = oyv[j] * S + ky - 1;
                    if ((unsigned)iy >= (unsigned)IH) continue;
                    const float* srow = sc + iy * PADW;
                    int ixb = oxv[j] * S - 1;
                    float x0 = (ixb >= 0)       ? srow[ixb]     : 0.f;
                    float x1 =                    srow[ixb + 1];
                    float x2 = (ixb + 2 < IW)   ? srow[ixb + 2] : 0.f;
#pragma unroll
                    for (int i = 0; i < TOC; i++)
                        acc[i][j] = fmaf(wr[i][0], x0,
                                    fmaf(wr[i][1], x1,
                                    fmaf(wr[i][2], x2, acc[i][j])));
                }
            }
        }
    }
#pragma unroll
    for (int i = 0; i < TOC; i++) {
        float bv = fw[ex * PTOT + boff + oc0 + i];
#pragma unroll
        for (int j = 0; j < TOX; j++) {
            long o = (((long)n * OC + oc0 + i) * OH + oyv[j]) * OW + oxv[j];
            out[o] = fmaxf(acc[i][j] + bv, 0.f);
        }
    }
}

__global__ void k_conv_l4_test(const float* __restrict__ in, const float* __restrict__ fw,
                               float* __restrict__ out)
{
    constexpr int IC = 256, OC = 256;
    constexpr int PADW = 9;
    constexpr int ICH = 4;
    __shared__ float sx[ICH * 8 * PADW];
    __shared__ float sw[256 * 37];

    int n  = blockIdx.x;
    long ex = n / NL;
    int oc = threadIdx.x;
    const float* x     = in + (long)n * IC * 64;
    const float* wbase = fw + ex * PTOT + OFF_W4 + (long)oc * IC * 9;
    float* swp = sw + oc * 37;

    float acc[4][4];
#pragma unroll
    for (int oy = 0; oy < 4; oy++)
#pragma unroll
        for (int ox = 0; ox < 4; ox++) acc[oy][ox] = 0.f;

    for (int c0 = 0; c0 < IC; c0 += ICH) {
        __syncthreads();
        {
            int i = threadIdx.x;
            int ic = i >> 6, r = i & 63;
            sx[(ic * 8 + (r >> 3)) * PADW + (r & 7)] = x[(long)(c0 + ic) * 64 + r];
        }
        {
            const float* wp = wbase + c0 * 9;
#pragma unroll
            for (int k = 0; k < 36; k++) swp[k] = wp[k];
        }
        __syncthreads();
#pragma unroll
        for (int ic = 0; ic < ICH; ic++) {
            float wv[9];
#pragma unroll
            for (int k = 0; k < 9; k++) wv[k] = swp[ic * 9 + k];
            const float* sxc = sx + ic * 8 * PADW;
#pragma unroll
            for (int ky = 0; ky < 3; ky++) {
                float w0 = wv[ky * 3], w1 = wv[ky * 3 + 1], w2 = wv[ky * 3 + 2];
#pragma unroll
                for (int oy = 0; oy < 4; oy++) {
                    int iy = oy * 2 + ky - 1;
                    if ((unsigned)iy >= 8u) continue;
                    const float* xr = sxc + iy * PADW;
                    float xv[9];
#pragma unroll
                    for (int u = 0; u < 9; u++) {
                        int ix = u - 1;
                        xv[u] = ((unsigned)ix < 8u) ? xr[ix] : 0.f;
                    }
#pragma unroll
                    for (int ox = 0; ox < 4; ox++)
                        acc[oy][ox] = fmaf(w0, xv[2 * ox],
                                      fmaf(w1, xv[2 * ox + 1],
                                      fmaf(w2, xv[2 * ox + 2], acc[oy][ox])));
                }
            }
        }
    }
    float bv = fw[ex * PTOT + OFF_B4 + oc];
    float* op = out + ((long)n * OC + oc) * 16;
#pragma unroll
    for (int oy = 0; oy < 4; oy++)
#pragma unroll
        for (int ox = 0; ox < 4; ox++)
            op[oy * 4 + ox] = fmaxf(acc[oy][ox] + bv, 0.f);
}

__global__ void k_biasrelu(float* __restrict__ out, const float* __restrict__ fw,
                           int boff, int wdiv, int N, int OC, int OHW)
{
    int i = blockIdx.x * 256 + threadIdx.x;
    if (i >= N * OC * OHW) return;
    int oc = (i / OHW) % OC;
    long ex = (i / (OC * OHW)) / wdiv;
    out[i] = fmaxf(out[i] + fw[ex * PTOT + boff + oc], 0.f);
}

__global__ void k_gate(const float* __restrict__ a, const float* __restrict__ gate, int gstride,
                       float* __restrict__ o, int N)
{
    int i = blockIdx.x * 256 + threadIdx.x;
    if (i >= N * FEAT) return;
    int n = i / FEAT, m = i % FEAT;
    o[i] = a[i] * gate[(long)n * gstride + m];
}

__global__ void k_logit_init(const float* __restrict__ fw, int wdiv, float* __restrict__ logits, int N)
{
    int i = blockIdx.x * 256 + threadIdx.x;
    if (i >= N * NCLS) return;
    int cls = i % NCLS;
    long ex = (i / NCLS) / wdiv;
    logits[i] = fw[ex * PTOT + OFF_BO + cls];
}

__global__ void k_head_fwd_chunk(const float* __restrict__ feat, const float* __restrict__ fw,
                                 int wdiv, float* __restrict__ logits, int N)
{
    int gt = blockIdx.x * 256 + threadIdx.x;
    int warp = gt >> 5, lane = gt & 31;
    if (warp >= N * NCLS * 4) return;
    int ch = warp & 3; int w2 = warp >> 2;
    int cls = w2 % NCLS, n = w2 / NCLS;
    long ex = n / wdiv;
    const float* w = fw + ex * PTOT + OFF_WO + (long)cls * FEAT + ch * 1024;
    const float* f = feat + (long)n * FEAT + ch * 1024;
    float acc = 0.f;
#pragma unroll 8
    for (int m = lane; m < 1024; m += 32) acc = fmaf(w[m], f[m], acc);
#pragma unroll
    for (int o = 16; o; o >>= 1) acc += __shfl_down_sync(0xffffffffu, acc, o);
    if (!lane) atomicAdd(&logits[w2], acc);
}

__global__ void k_ce_grad(const float* __restrict__ logits, const int* __restrict__ y,
                          int ystride, int yoff, float* __restrict__ dlogit,
                          float* __restrict__ fw, const float* __restrict__ log_lr)
{
    int b = blockIdx.x, tid = threadIdx.x;
    __shared__ float red[128];
    float v = (tid < NCLS) ? logits[b * NCLS + tid] : -1e30f;
    red[tid] = v; __syncthreads();
    for (int s = 64; s > 0; s >>= 1) { if (tid < s) red[tid] = fmaxf(red[tid], red[tid + s]); __syncthreads(); }
    float m = red[0]; __syncthreads();
    float e = (tid < NCLS) ? expf(v - m) : 0.f;
    red[tid] = e; __syncthreads();
    for (int s = 64; s > 0; s >>= 1) { if (tid < s) red[tid] += red[tid + s]; __syncthreads(); }
    float sum = red[0];
    int label = y[b * ystride + yoff];
    if (tid < NCLS) {
        float dl = e / sum - (tid == label ? 1.f : 0.f);
        dlogit[b * NCLS + tid] = dl;
        fw[(long)b * PTOT + OFF_BO + tid] -= expf(*log_lr) * dl;
    }
}

__global__ void k_head_bwd_f_chunk(const float* __restrict__ dlogit, const float* __restrict__ fw,
                                   float* __restrict__ raw)
{
    int i = blockIdx.x * 256 + threadIdx.x;
    if (i >= NB * 4 * FEAT) return;
    int m = i % FEAT; int t = i / FEAT;
    int ch = t % 4; int b = t / 4;
    const float* w  = fw + (long)b * PTOT + OFF_WO + m + (long)(ch * 25) * FEAT;
    const float* dl = dlogit + b * NCLS + ch * 25;
    float acc = 0.f;
#pragma unroll
    for (int n = 0; n < 25; n++) acc = fmaf(w[(long)n * FEAT], dl[n], acc);
    atomicAdd(&raw[(long)b * FEAT + m], acc);
}

__global__ void k_mask_gate(const float* __restrict__ raw, const float* __restrict__ a5,
                            const float* __restrict__ gate, int gstride, float* __restrict__ dz)
{
    int i = blockIdx.x * 256 + threadIdx.x;
    if (i >= NB * FEAT) return;
    int m = i % FEAT, b = i / FEAT;
    dz[i] = (a5[i] > 0.f) ? raw[i] * gate[(long)b * gstride + m] : 0.f;
}

__global__ void k_head_upd_w(const float* __restrict__ dlogit, const float* __restrict__ feat,
                             float* __restrict__ fw, const float* __restrict__ log_lr)
{
    int i = blockIdx.x * 256 + threadIdx.x;
    if (i >= NB * NCLS * FEAT) return;
    int m = i % FEAT; int t = i / FEAT;
    int cls = t % NCLS; int b = t / NCLS;
    fw[(long)b * PTOT + OFF_WO + (long)cls * FEAT + m] -=
        expf(*log_lr) * dlogit[b * NCLS + cls] * feat[(long)b * FEAT + m];
}

__global__ void k_bwd_b_upd(const float* __restrict__ dz, float* __restrict__ fw,
                            const float* __restrict__ log_lr, int boff, int OC, int OHW)
{
    int gt = blockIdx.x * 256 + threadIdx.x;
    int warp = gt >> 5, lane = gt & 31;
    if (warp >= NB * OC) return;
    int oc = warp % OC, b = warp / OC;
    const float* p = dz + ((long)b * OC + oc) * OHW;
    float acc = 0.f;
    for (int i = lane; i < OHW; i += 32) acc += p[i];
#pragma unroll
    for (int o = 16; o; o >>= 1) acc += __shfl_down_sync(0xffffffffu, acc, o);
    if (!lane) fw[(long)b * PTOT + boff + oc] -= expf(*log_lr) * acc;
}

template<int S>
__global__ void k_bwd_w_warp(const float* __restrict__ dz, const float* __restrict__ xin, long xstride,
                             float* __restrict__ fw, const float* __restrict__ log_lr, int woff,
                             int IC, int OC, int IH, int IW, int OH, int OW, int NCH)
{
    long gt = blockIdx.x * 256L + threadIdx.x;
    long w = gt >> 5; int lane = (int)(gt & 31);
    if (w >= (long)NB * OC * IC * NCH) return;
    int c  = (int)(w % NCH); long t = w / NCH;
    int ic = (int)(t % IC); t /= IC;
    int oc = (int)(t % OC); int b = (int)(t / OC);
    int CH = OH / NCH;
    const float* x = xin + (long)b * xstride + (long)ic * IH * IW;
    const float* z = dz + ((long)b * OC + oc) * OH * OW;
    float acc[9];
#pragma unroll
    for (int k = 0; k < 9; k++) acc[k] = 0.f;
    int oybase = c * CH;
    int npix = CH * OW;
    for (int p = lane; p < npix; p += 32) {
        int oy = oybase + p / OW;
        int ox = p % OW;
        float zv = z[oy * OW + ox];
#pragma unroll
        for (int ky = 0; ky < 3; ky++) {
            int iy = oy * S + ky - 1;
            if ((unsigned)iy >= (unsigned)IH) continue;
            const float* xr = x + iy * IW;
            int ixb = ox * S - 1;
#pragma unroll
            for (int kx = 0; kx < 3; kx++) {
                int ix = ixb + kx;
                if ((unsigned)ix < (unsigned)IW)
                    acc[ky * 3 + kx] = fmaf(zv, xr[ix], acc[ky * 3 + kx]);
            }
        }
    }
    float nlr = -expf(*log_lr);
    float* g = fw + (long)b * PTOT + woff + ((long)oc * IC + ic) * 9;
#pragma unroll
    for (int k = 0; k < 9; k++) {
        float v = acc[k];
#pragma unroll
        for (int o = 16; o; o >>= 1) v += __shfl_down_sync(0xffffffffu, v, o);
        if (!lane) atomicAdd(g + k, nlr * v);
    }
}

__global__ void k_bwd_x_chunk(const float* __restrict__ dz, const float* __restrict__ fw, int woff,
                              float* __restrict__ raw,
                              int IC, int OC, int IH, int IW, int OH, int OW,
                              int NCHUNK, int OCH)
{
    int nix = IW >> 2;
    int base = NB * IC * IH * nix;
    int idx = blockIdx.x * 256 + threadIdx.x;
    if (idx >= base * NCHUNK) return;
    int ch = idx / base; int r = idx % base;
    int ix0 = (r % nix) * 4; int t = r / nix;
    int iy = t % IH; t /= IH;
    int ic = t % IC; int b = t / IC;
    long pix = (((long)b * IC + ic) * IH + iy) * IW + ix0;

    float acc0 = 0.f, acc1 = 0.f, acc2 = 0.f, acc3 = 0.f;
    int ox0p = ix0 >> 1;
    bool ok2 = (ox0p + 2 < OW), ok1 = (ox0p + 1 < OW);

    int oyv[3]; bool kyok[3];
#pragma unroll
    for (int ky = 0; ky < 3; ky++) {
        int ty = iy + 1 - ky;
        kyok[ky] = (ty >= 0) && !(ty & 1) && ((ty >> 1) < OH);
        oyv[ky] = ty >> 1;
    }
    const float* wb = fw + (long)b * PTOT + woff + (long)ic * 9;
    const float* zb = dz + (long)b * OC * OH * OW;
    int oc0 = ch * OCH;
    for (int oc = oc0; oc < oc0 + OCH; oc++) {
        const float* wp = wb + (long)oc * IC * 9;
        const float* zp = zb + (long)oc * OH * OW;
#pragma unroll
        for (int ky = 0; ky < 3; ky++) {
            if (!kyok[ky]) continue;
            const float* zr = zp + oyv[ky] * OW;
            float d0 = zr[ox0p];
            float d1 = ok1 ? zr[ox0p + 1] : 0.f;
            float d2 = ok2 ? zr[ox0p + 2] : 0.f;
            float wk0 = wp[ky * 3 + 0], wk1 = wp[ky * 3 + 1], wk2 = wp[ky * 3 + 2];
            acc0 = fmaf(wk1, d0, acc0);
            acc1 = fmaf(wk0, d1, fmaf(wk2, d0, acc1));
            acc2 = fmaf(wk1, d1, acc2);
            acc3 = fmaf(wk0, d2, fmaf(wk2, d1, acc3));
        }
    }
    atomicAdd(&raw[pix],     acc0);
    atomicAdd(&raw[pix + 1], acc1);
    atomicAdd(&raw[pix + 2], acc2);
    atomicAdd(&raw[pix + 3], acc3);
}

__global__ void k_mask(const float* __restrict__ raw, const float* __restrict__ act,
                       float* __restrict__ dz, int count)
{
    int i = blockIdx.x * 256 + threadIdx.x;
    if (i < count) dz[i] = (act[i] > 0.f) ? raw[i] : 0.f;
}

__global__ void k_loss_eval(const float* __restrict__ logits, const int* __restrict__ y,
                            const float* __restrict__ log_lr, float* __restrict__ out)
{
    int e = blockIdx.x, tid = threadIdx.x;
    __shared__ float rv[128];
    __shared__ int   ri[128];
    float v = (tid < NCLS) ? logits[e * NCLS + tid] : -1e30f;
    rv[tid] = v; ri[tid] = tid; __syncthreads();
    for (int s = 64; s > 0; s >>= 1) {
        if (tid < s) {
            if (rv[tid + s] > rv[tid] || (rv[tid + s] == rv[tid] && ri[tid + s] < ri[tid])) {
                rv[tid] = rv[tid + s]; ri[tid] = ri[tid + s];
            }
        }
        __syncthreads();
    }
    float m = rv[0]; int amax = ri[0]; __syncthreads();
    float ex = (tid < NCLS) ? expf(v - m) : 0.f;
    rv[tid] = ex; __syncthreads();
    for (int s = 64; s > 0; s >>= 1) { if (tid < s) rv[tid] += rv[tid + s]; __syncthreads(); }
    if (tid == 0) {
        float lse = m + logf(rv[0]);
        int label = y[e];
        out[e]        = lse - logits[e * NCLS + label];
        out[129 + e]  = (amax == label) ? 1.f : 0.f;
        if (e == 0) out[128] = expf(*log_lr);
    }
}

// ---------------- launcher ----------------
struct LC { int ic, oc, ih, iw, oh, ow, s; };
static const LC lc[5] = {
    {  3,  32, 64, 64, 64, 64, 1},
    { 32,  64, 64, 64, 32, 32, 2},
    { 64, 128, 32, 32, 16, 16, 2},
    {128, 256, 16, 16,  8,  8, 2},
    {256, 256,  8,  8,  4,  4, 2},
};
static const int woffs[5] = {OFF_W0, OFF_W1, OFF_W2, OFF_W3, OFF_W4};
static const int boffs[5] = {OFF_B0, OFF_B1, OFF_B2, OFF_B3, OFF_B4};

static inline unsigned GRID(long n) { return (unsigned)((n + 255) / 256); }

extern "C" void kernel_launch(void* const* d_in, const int* in_sizes, int n_in,
                              void* d_out, int out_size)
{
    const float* pw[12];
    for (int i = 0; i < 12; i++) pw[i] = (const float*)d_in[i];
    const float* log_lr     = (const float*)d_in[12];
    const float* train_x    = (const float*)d_in[13];
    const float* test_x     = (const float*)d_in[14];
    const float* train_gate = (const float*)d_in[15];
    const float* test_gate  = (const float*)d_in[16];
    const int*   train_y    = (const int*)d_in[17];
    const int*   test_y     = (const int*)d_in[18];
    float* out = (float*)d_out;

    float *fw, *a1, *a2, *a3, *a4, *a5, *feat, *logit, *dlogit, *d1, *d2, *za, *zb, *zc, *zd, *ta, *tb;
    cudaGetSymbolAddress((void**)&fw,     g_fw);
    cudaGetSymbolAddress((void**)&a1,     g_a1);
    cudaGetSymbolAddress((void**)&a2,     g_a2);
    cudaGetSymbolAddress((void**)&a3,     g_a3);
    cudaGetSymbolAddress((void**)&a4,     g_a4);
    cudaGetSymbolAddress((void**)&a5,     g_a5);
    cudaGetSymbolAddress((void**)&feat,   g_feat);
    cudaGetSymbolAddress((void**)&logit,  g_logit);
    cudaGetSymbolAddress((void**)&dlogit, g_dlogit);
    cudaGetSymbolAddress((void**)&d1,     g_d1);
    cudaGetSymbolAddress((void**)&d2,     g_d2);
    cudaGetSymbolAddress((void**)&za,     g_za);
    cudaGetSymbolAddress((void**)&zb,     g_zb);
    cudaGetSymbolAddress((void**)&zc,     g_zc);
    cudaGetSymbolAddress((void**)&zd,     g_zd);
    cudaGetSymbolAddress((void**)&ta,     g_ta);
    cudaGetSymbolAddress((void**)&tb,     g_tb);

    static cudaStream_t s_side = nullptr;
    static cudaEvent_t  ev_fork = nullptr, ev_fz = nullptr, ev_h = nullptr,
                        ev_x1 = nullptr, ev_x2 = nullptr, ev_x3 = nullptr, ev_x4 = nullptr,
                        ev_mg = nullptr, ev_m4 = nullptr, ev_m3 = nullptr, ev_m1 = nullptr,
                        ev_z3 = nullptr, ev_z2 = nullptr, ev_z1 = nullptr, ev_done = nullptr;
    if (!s_side) {
        cudaStreamCreateWithFlags(&s_side, cudaStreamNonBlocking);
        cudaEventCreateWithFlags(&ev_fork, cudaEventDisableTiming);
        cudaEventCreateWithFlags(&ev_fz,   cudaEventDisableTiming);
        cudaEventCreateWithFlags(&ev_h,    cudaEventDisableTiming);
        cudaEventCreateWithFlags(&ev_x1,   cudaEventDisableTiming);
        cudaEventCreateWithFlags(&ev_x2,   cudaEventDisableTiming);
        cudaEventCreateWithFlags(&ev_x3,   cudaEventDisableTiming);
        cudaEventCreateWithFlags(&ev_x4,   cudaEventDisableTiming);
        cudaEventCreateWithFlags(&ev_mg,   cudaEventDisableTiming);
        cudaEventCreateWithFlags(&ev_m4,   cudaEventDisableTiming);
        cudaEventCreateWithFlags(&ev_m3,   cudaEventDisableTiming);
        cudaEventCreateWithFlags(&ev_m1,   cudaEventDisableTiming);
        cudaEventCreateWithFlags(&ev_z3,   cudaEventDisableTiming);
        cudaEventCreateWithFlags(&ev_z2,   cudaEventDisableTiming);
        cudaEventCreateWithFlags(&ev_z1,   cudaEventDisableTiming);
        cudaEventCreateWithFlags(&ev_done, cudaEventDisableTiming);
    }
    cudaEvent_t ev_x[5] = {nullptr, ev_x1, ev_x2, ev_x3, ev_x4};

    float* acts[6] = {nullptr, a1, a2, a3, a4, a5};
    float* zbuf[5] = {zd, zc, zb, za, d1};
    float* rawb[5] = {nullptr, d2, ta, d2, ta};
    long insz[5];
    for (int j = 0; j < 5; j++) insz[j] = (long)NB * lc[j].ic * lc[j].ih * lc[j].iw;

    const int f_ich[5] = {0, 8, 8, 8, 4};
    const int wnch[5] = {16, 4, 2, 1, 1};

    k_bcast_all<<<GRID((long)NB * PTOT), 256>>>(pw[0], pw[1], pw[2], pw[3], pw[4], pw[5],
                                                pw[6], pw[7], pw[8], pw[9], pw[10], pw[11], fw);

    auto fwd_inner_conv = [&](int j, const float* in, float* o) {
        const LC& L = lc[j];
        int ich = f_ich[j], nch = L.ic / ich;
        long instr = (long)L.ic * L.ih * L.iw;
        long tot = (long)NB * (L.oc / 4) * L.oh * (L.ow / 4) * nch;
        k_conv_fwd_chunk<2, 4, 4><<<GRID(tot), 256>>>(in, instr, fw, woffs[j], 1, o,
            NB, L.ic, L.oc, L.ih, L.iw, L.oh, L.ow, nch, ich);
        long osz = (long)NB * L.oc * L.oh * L.ow;
        k_biasrelu<<<GRID(osz), 256>>>(o, fw, boffs[j], 1, NB, L.oc, L.oh * L.ow);
    };

    for (int t = 0; t < NT; t++) {
        const float* in0 = train_x + (long)t * CHW;

        // fork: memsets on side while L0 conv runs on main
        cudaEventRecord(ev_fork, 0);
        cudaStreamWaitEvent(s_side, ev_fork, 0);
        cudaMemsetAsync(a2, 0, (long)NB * 65536 * sizeof(float), s_side);
        cudaMemsetAsync(a3, 0, (long)NB * 32768 * sizeof(float), s_side);
        cudaMemsetAsync(a4, 0, (long)NB * 16384 * sizeof(float), s_side);
        cudaMemsetAsync(a5, 0, (long)NB * 4096 * sizeof(float), s_side);
        cudaMemsetAsync(d2, 0, (long)NB * FEAT * sizeof(float), s_side);   // head raw
        cudaMemsetAsync(ta, 0, insz[4] * sizeof(float), s_side);           // L4 raw
        cudaEventRecord(ev_fz, s_side);
        {
            long tot = (long)NB * (32 / 4) * 64 * (64 / 4);
            k_conv_fwd_t<1, 4, 4><<<GRID(tot), 256>>>(in0, (long)NT * CHW, fw, OFF_W0, OFF_B0, 1, a1,
                                                      NB, 3, 32, 64, 64, 64, 64);
        }
        cudaStreamWaitEvent(0, ev_fz, 0);
        fwd_inner_conv(1, a1, a2);
        fwd_inner_conv(2, a2, a3);
        fwd_inner_conv(3, a3, a4);
        fwd_inner_conv(4, a4, a5);
        k_gate<<<GRID((long)NB * FEAT), 256>>>(a5, train_gate + (long)t * FEAT, NT * FEAT, feat, NB);
        k_logit_init<<<GRID((long)NB * NCLS), 256>>>(fw, 1, logit, NB);
        k_head_fwd_chunk<<<GRID((long)NB * NCLS * 4 * 32), 256>>>(feat, fw, 1, logit, NB);
        k_ce_grad<<<NB, 128>>>(logit, train_y, NT, t, dlogit, fw, log_lr);
        k_head_bwd_f_chunk<<<GRID((long)NB * 4 * FEAT), 256>>>(dlogit, fw, d2);
        cudaEventRecord(ev_h, 0);
        cudaStreamWaitEvent(s_side, ev_h, 0);
        k_head_upd_w<<<GRID((long)NB * NCLS * FEAT), 256, 0, s_side>>>(dlogit, feat, fw, log_lr);
        k_mask_gate<<<GRID((long)NB * FEAT), 256>>>(d2, a5, train_gate + (long)t * FEAT, NT * FEAT, d1);
        cudaEventRecord(ev_mg, 0);
        cudaStreamWaitEvent(s_side, ev_mg, 0);
        cudaMemsetAsync(d2, 0, insz[3] * sizeof(float), s_side);
        cudaEventRecord(ev_z3, s_side);

        for (int j = 4; j >= 1; j--) {
            const LC& L = lc[j];
            long instr = (long)L.ic * L.ih * L.iw;
            if (j == 3) cudaStreamWaitEvent(0, ev_z3, 0);
            if (j == 2) cudaStreamWaitEvent(0, ev_z2, 0);
            if (j == 1) cudaStreamWaitEvent(0, ev_z1, 0);
            {
                int och = 16, nch = L.oc / och;
                long tot = (long)NB * L.ic * L.ih * (L.iw / 4) * nch;
                k_bwd_x_chunk<<<GRID(tot), 256>>>(zbuf[j], fw, woffs[j], rawb[j],
                    L.ic, L.oc, L.ih, L.iw, L.oh, L.ow, nch, och);
            }
            cudaEventRecord(ev_x[j], 0);
            cudaStreamWaitEvent(s_side, ev_x[j], 0);
            k_bwd_b_upd<<<GRID((long)NB * L.oc * 32), 256, 0, s_side>>>(zbuf[j], fw, log_lr,
                                                                        boffs[j], L.oc, L.oh * L.ow);
            {
                long warps = (long)NB * L.oc * L.ic * wnch[j];
                k_bwd_w_warp<2><<<GRID(warps * 32), 256, 0, s_side>>>(zbuf[j], acts[j], instr,
                    fw, log_lr, woffs[j], L.ic, L.oc, L.ih, L.iw, L.oh, L.ow, wnch[j]);
            }
            k_mask<<<GRID(insz[j]), 256>>>(rawb[j], acts[j], zbuf[j - 1], (int)insz[j]);
            if (j == 4) {
                cudaEventRecord(ev_m4, 0);
                cudaStreamWaitEvent(s_side, ev_m4, 0);
                cudaMemsetAsync(ta, 0, insz[2] * sizeof(float), s_side);
                cudaEventRecord(ev_z2, s_side);
            } else if (j == 3) {
                cudaEventRecord(ev_m3, 0);
                cudaStreamWaitEvent(s_side, ev_m3, 0);
                cudaMemsetAsync(d2, 0, insz[1] * sizeof(float), s_side);
                cudaEventRecord(ev_z1, s_side);
            }
        }
        cudaEventRecord(ev_m1, 0);
        cudaStreamWaitEvent(s_side, ev_m1, 0);
        k_bwd_b_upd<<<GRID((long)NB * 32 * 32), 256, 0, s_side>>>(zbuf[0], fw, log_lr, OFF_B0, 32, 4096);
        {
            long warps = (long)NB * 32 * 3 * wnch[0];
            k_bwd_w_warp<1><<<GRID(warps * 32), 256, 0, s_side>>>(zbuf[0], in0, (long)NT * CHW,
                fw, log_lr, OFF_W0, 3, 32, 64, 64, 64, 64, wnch[0]);
        }
        cudaEventRecord(ev_done, s_side);
        cudaStreamWaitEvent(0, ev_done, 0);
    }

    // -------- test forward --------
    {
        long tot = (long)NTEST * (32 / 4) * 64 * (64 / 4);
        k_conv_fwd_t<1, 4, 4><<<GRID(tot), 256>>>(test_x, (long)CHW, fw, OFF_W0, OFF_B0, NL, ta,
                                                  NTEST, 3, 32, 64, 64, 64, 64);
    }
    k_conv_smem<2, 4, 64, 64, 32, 32, 8, 4, 8><<<NTEST * (64 / 8), 256>>>(
        ta, fw, OFF_W1, OFF_B1, NL, tb, 32, 64);
    k_conv_smem<2, 8, 32, 32, 16, 16, 8, 4, 32><<<NTEST * (128 / 32), 256>>>(
        tb, fw, OFF_W2, OFF_B2, NL, ta, 64, 128);
    k_conv_smem<2, 32, 16, 16, 8, 8, 8, 4, 128><<<NTEST * (256 / 128), 256>>>(
        ta, fw, OFF_W3, OFF_B3, NL, tb, 128, 256);
    k_conv_l4_test<<<NTEST, 256>>>(tb, fw, ta);
    k_gate<<<GRID((long)NTEST * FEAT), 256>>>(ta, test_gate, FEAT, tb, NTEST);
    k_logit_init<<<GRID((long)NTEST * NCLS), 256>>>(fw, NL, out + 257, NTEST);
    k_head_fwd_chunk<<<GRID((long)NTEST * NCLS * 4 * 32), 256>>>(tb, fw, NL, out + 257, NTEST);
    k_loss_eval<<<NTEST, 128>>>(out + 257, test_y, log_lr, out);
}